// round 1
// baseline (speedup 1.0000x reference)
#include <cuda_runtime.h>

// Problem constants
// x:    (8,128,128,64)  NHWC
// Woff: (3,3,64,18)     HWIO
// boff: (18)
// W:    (3,3,576,128)   HWIO  -> flat (5184,128) GEMM B matrix
// b:    (128)
// out:  (8,128,128,128) float32

#define KTOT 5184
#define NCH  648          // KTOT / 8

// offsets scratch: (B,H,W,18) = 9.4MB
__device__ float g_off[8 * 128 * 128 * 18];

// ------------------------------------------------------------------
// K1: offsets = conv3x3(x, Woff) + boff
// One block per (b,h) image row. 128 threads = 128 w positions.
// ------------------------------------------------------------------
__global__ __launch_bounds__(128) void offsets_kernel(
    const float* __restrict__ x, const float* __restrict__ Woff,
    const float* __restrict__ boff) {
  __shared__ float xs[3][128][17];   // 3 rows x 128 w x 16 c (padded 17)
  __shared__ float wofs[9][16][18];  // (r,s) x c-chunk x o

  const int bh = blockIdx.x;  // 0..1023
  const int b = bh >> 7, h = bh & 127;
  const int w = threadIdx.x;

  float acc[18];
#pragma unroll
  for (int o = 0; o < 18; o++) acc[o] = 0.f;

#pragma unroll 1
  for (int cc = 0; cc < 64; cc += 16) {
    // load 3 rows x 128 w x 16 c of x (zero outside image)
    for (int fid = threadIdx.x; fid < 1536; fid += 128) {
      int r = fid / 512;
      int rem = fid - r * 512;
      int ww = rem >> 2;
      int cq = (rem & 3) * 4;
      int y = h + r - 1;
      float4 v = make_float4(0.f, 0.f, 0.f, 0.f);
      if ((unsigned)y < 128u)
        v = *(const float4*)&x[(((b * 128 + y) * 128 + ww) * 64) + cc + cq];
      xs[r][ww][cq + 0] = v.x;
      xs[r][ww][cq + 1] = v.y;
      xs[r][ww][cq + 2] = v.z;
      xs[r][ww][cq + 3] = v.w;
    }
    // load Woff chunk: dest [rs][c][o], src (rs*64+cc+c)*18+o
    for (int idx = threadIdx.x; idx < 9 * 16 * 18; idx += 128) {
      int rs = idx / 288;
      ((float*)wofs)[idx] = Woff[idx + rs * 864 + cc * 18];
    }
    __syncthreads();

#pragma unroll 1
    for (int rs = 0; rs < 9; rs++) {
      int r = rs / 3;
      int s = rs - r * 3;
      int wp = w + s - 1;
      if ((unsigned)wp < 128u) {
#pragma unroll
        for (int c = 0; c < 16; c++) {
          float v = xs[r][wp][c];
#pragma unroll
          for (int o = 0; o < 18; o++) acc[o] += v * wofs[rs][c][o];
        }
      }
    }
    __syncthreads();
  }

  int base = (bh * 128 + w) * 18;
#pragma unroll
  for (int o = 0; o < 18; o++) g_off[base + o] = acc[o] + boff[o];
}

// ------------------------------------------------------------------
// Bilinear sample of 4 consecutive channels at (b, y, wp), tap ts.
// Mirrors the reference exactly (clip -> floor -> clipped-corner weights).
// ------------------------------------------------------------------
__device__ __forceinline__ float4 bilin4(const float* __restrict__ x, int b,
                                         int y, int wp, int ts, int c0) {
  int pix = (b * 128 + y) * 128 + wp;
  float ox = g_off[pix * 18 + 2 * ts];
  float oy = g_off[pix * 18 + 2 * ts + 1];
  float lx = (float)(wp + (ts % 3) - 1) + ox;
  float ly = (float)(y + (ts / 3) - 1) + oy;
  lx = fminf(fmaxf(lx, 0.f), 127.f);
  ly = fminf(fmaxf(ly, 0.f), 127.f);
  float x0f = floorf(lx), y0f = floorf(ly);
  int xi0 = (int)x0f, yi0 = (int)y0f;
  int xi1 = min(xi0 + 1, 127), yi1 = min(yi0 + 1, 127);
  float x1f = (float)xi1, y1f = (float)yi1;
  float dx0 = lx - x0f, dy0 = ly - y0f;
  float dx1 = x1f - lx, dy1 = y1f - ly;
  float wa = dx1 * dy1, wb = dx1 * dy0, wc = dx0 * dy1, wd = dx0 * dy0;

  const float* xb = x + ((size_t)b << 20);  // b * 128*128*64
  int r0 = yi0 << 13, r1 = yi1 << 13;       // y * 128*64
  int cx0 = (xi0 << 6) + c0, cx1 = (xi1 << 6) + c0;
  float4 Ia = *(const float4*)&xb[r0 + cx0];
  float4 Ib = *(const float4*)&xb[r1 + cx0];
  float4 Ic = *(const float4*)&xb[r0 + cx1];
  float4 Id = *(const float4*)&xb[r1 + cx1];
  float4 rv;
  rv.x = wa * Ia.x + wb * Ib.x + wc * Ic.x + wd * Id.x;
  rv.y = wa * Ia.y + wb * Ib.y + wc * Ic.y + wd * Id.y;
  rv.z = wa * Ia.z + wb * Ib.z + wc * Ic.z + wd * Id.z;
  rv.w = wa * Ia.w + wb * Ib.w + wc * Ic.w + wd * Id.w;
  return rv;
}

// A-tile element: im2col of the *sampled* tensor, computed on the fly.
// kn = k-chunk base (multiple of 8). Thread supplies (apix, akq).
__device__ __forceinline__ float4 loadA_elem(const float* __restrict__ x, int b,
                                             int h, int apix, int akq, int kn) {
  int tap = kn / 576;            // outer conv tap (r,s)
  int rem = kn - tap * 576;
  int ts = rem >> 6;             // bilinear tap
  int c0 = (rem & 63) + akq;     // channel
  int r = tap / 3;
  int s = tap - r * 3;
  int y = h + r - 1;
  int wp = apix + s - 1;
  if (((unsigned)y < 128u) && ((unsigned)wp < 128u))
    return bilin4(x, b, y, wp, ts, c0);
  return make_float4(0.f, 0.f, 0.f, 0.f);
}

#define FMA2(d, a, bb) \
  asm("fma.rn.f32x2 %0, %1, %2, %0;" : "+l"(d) : "l"(a), "l"(bb))

// ------------------------------------------------------------------
// K2: fused deformable-sample + implicit GEMM.
// BM=128 (one image row), BN=128 (all filters), BK=8.
// 256 threads, 8x8 outputs each via packed f32x2 FMA (4 m-pairs x 8 n).
// ------------------------------------------------------------------
__global__ __launch_bounds__(256, 2) void gemm_kernel(
    const float* __restrict__ x, const float* __restrict__ Wm,
    const float* __restrict__ bias, float* __restrict__ out) {
  __shared__ __align__(16) float As[2][8][132];  // [k][pix], padded
  __shared__ __align__(16) float Bs[2][8][256];  // [k][2f] duplicated pairs

  const int tid = threadIdx.x;
  const int bh = blockIdx.x;  // (b,h) row
  const int b = bh >> 7, h = bh & 127;
  const int tm8 = (tid >> 4) * 8;    // output rows base
  const int tn16 = (tid & 15) * 16;  // dup-index base (= 2 * n_base)
  const int apix = tid >> 1;         // A-load pixel 0..127
  const int akq = (tid & 1) * 4;     // A-load k offset {0,4}
  const int bk = tid >> 5;           // B-load k row 0..7
  const int bf = (tid & 31) * 4;     // B-load filter base

  unsigned long long acc[4][8];
#pragma unroll
  for (int j = 0; j < 8; j++) {
    float bv = bias[(tn16 >> 1) + j];
    unsigned long long d;
    asm("mov.b64 %0, {%1, %1};" : "=l"(d) : "f"(bv));
#pragma unroll
    for (int i = 0; i < 4; i++) acc[i][j] = d;
  }

  float4 av, wv;

  // prefetch chunk 0
  av = loadA_elem(x, b, h, apix, akq, 0);
  wv = *(const float4*)&Wm[(size_t)bk * 128 + bf];
  // store buffer 0
  {
    As[0][akq + 0][apix] = av.x;
    As[0][akq + 1][apix] = av.y;
    As[0][akq + 2][apix] = av.z;
    As[0][akq + 3][apix] = av.w;
    unsigned long long d0, d1, d2, d3;
    asm("mov.b64 %0, {%1, %1};" : "=l"(d0) : "f"(wv.x));
    asm("mov.b64 %0, {%1, %1};" : "=l"(d1) : "f"(wv.y));
    asm("mov.b64 %0, {%1, %1};" : "=l"(d2) : "f"(wv.z));
    asm("mov.b64 %0, {%1, %1};" : "=l"(d3) : "f"(wv.w));
    ulonglong2* Bd = (ulonglong2*)&Bs[0][bk][2 * bf];
    Bd[0] = make_ulonglong2(d0, d1);
    Bd[1] = make_ulonglong2(d2, d3);
  }
  __syncthreads();

  for (int ci = 0; ci < NCH; ci++) {
    const int cur = ci & 1;
    const bool more = (ci + 1 < NCH);
    if (more) {
      av = loadA_elem(x, b, h, apix, akq, (ci + 1) * 8);
      wv = *(const float4*)&Wm[(size_t)((ci + 1) * 8 + bk) * 128 + bf];
    }

    const float* Abase = &As[cur][0][0];
    const float* Bbase = &Bs[cur][0][0];
#pragma unroll
    for (int k = 0; k < 8; k++) {
      ulonglong2 a0 = *(const ulonglong2*)(Abase + k * 132 + tm8);
      ulonglong2 a1 = *(const ulonglong2*)(Abase + k * 132 + tm8 + 4);
      ulonglong2 b0 = *(const ulonglong2*)(Bbase + k * 256 + tn16);
      ulonglong2 b1 = *(const ulonglong2*)(Bbase + k * 256 + tn16 + 4);
      ulonglong2 b2 = *(const ulonglong2*)(Bbase + k * 256 + tn16 + 8);
      ulonglong2 b3 = *(const ulonglong2*)(Bbase + k * 256 + tn16 + 12);
      unsigned long long ap[4] = {a0.x, a0.y, a1.x, a1.y};
      unsigned long long bd[8] = {b0.x, b0.y, b1.x, b1.y,
                                  b2.x, b2.y, b3.x, b3.y};
#pragma unroll
      for (int i = 0; i < 4; i++)
#pragma unroll
        for (int j = 0; j < 8; j++) FMA2(acc[i][j], ap[i], bd[j]);
    }

    if (more) {
      const int nb = cur ^ 1;
      As[nb][akq + 0][apix] = av.x;
      As[nb][akq + 1][apix] = av.y;
      As[nb][akq + 2][apix] = av.z;
      As[nb][akq + 3][apix] = av.w;
      unsigned long long d0, d1, d2, d3;
      asm("mov.b64 %0, {%1, %1};" : "=l"(d0) : "f"(wv.x));
      asm("mov.b64 %0, {%1, %1};" : "=l"(d1) : "f"(wv.y));
      asm("mov.b64 %0, {%1, %1};" : "=l"(d2) : "f"(wv.z));
      asm("mov.b64 %0, {%1, %1};" : "=l"(d3) : "f"(wv.w));
      ulonglong2* Bd = (ulonglong2*)&Bs[nb][bk][2 * bf];
      Bd[0] = make_ulonglong2(d0, d1);
      Bd[1] = make_ulonglong2(d2, d3);
    }
    __syncthreads();
  }

  // epilogue: unpack f32x2 accumulators, vector stores
  float* outp = out + (size_t)bh * (128 * 128);
  const int nbase = tn16 >> 1;  // n = tn*8
#pragma unroll
  for (int i = 0; i < 4; i++) {
    float lo[8], hi[8];
#pragma unroll
    for (int j = 0; j < 8; j++)
      asm("mov.b64 {%0, %1}, %2;" : "=f"(lo[j]), "=f"(hi[j]) : "l"(acc[i][j]));
    int m0 = tm8 + 2 * i;
    *(float4*)&outp[m0 * 128 + nbase] = make_float4(lo[0], lo[1], lo[2], lo[3]);
    *(float4*)&outp[m0 * 128 + nbase + 4] =
        make_float4(lo[4], lo[5], lo[6], lo[7]);
    *(float4*)&outp[(m0 + 1) * 128 + nbase] =
        make_float4(hi[0], hi[1], hi[2], hi[3]);
    *(float4*)&outp[(m0 + 1) * 128 + nbase + 4] =
        make_float4(hi[4], hi[5], hi[6], hi[7]);
  }
}

extern "C" void kernel_launch(void* const* d_in, const int* in_sizes, int n_in,
                              void* d_out, int out_size) {
  (void)in_sizes;
  (void)n_in;
  (void)out_size;
  const float* x = (const float*)d_in[0];
  const float* Woff = (const float*)d_in[1];
  const float* boff = (const float*)d_in[2];
  const float* Wm = (const float*)d_in[3];
  const float* bias = (const float*)d_in[4];
  float* out = (float*)d_out;

  offsets_kernel<<<1024, 128>>>(x, Woff, boff);
  gemm_kernel<<<1024, 256>>>(x, Wm, bias, out);
}

// round 3
// speedup vs baseline: 3.1708x; 3.1708x over previous
#include <cuda_runtime.h>

// x:    (8,128,128,64)  NHWC
// Woff: (3,3,64,18)     HWIO
// boff: (18)
// W:    (3,3,576,128)   HWIO -> flat (5184,128)
// b:    (128)
// out:  (8,128,128,128) float32

#define NCH 648  // 5184 / 8

// scratch
__device__ float g_off[8 * 128 * 128 * 18];            // (pixel, 9 taps, 2)
__device__ float g_samp[8 * 128 * 128 * 9 * 64];       // (pixel, ts, c) 302MB

// ------------------------------------------------------------------
// K1: offsets = conv3x3(x, Woff) + boff. One block per (b,h) row.
// ------------------------------------------------------------------
__global__ __launch_bounds__(128) void offsets_kernel(
    const float* __restrict__ x, const float* __restrict__ Woff,
    const float* __restrict__ boff) {
  __shared__ float xs[3][128][17];
  __shared__ float wofs[9][16][18];

  const int bh = blockIdx.x;
  const int b = bh >> 7, h = bh & 127;
  const int w = threadIdx.x;

  float acc[18];
#pragma unroll
  for (int o = 0; o < 18; o++) acc[o] = 0.f;

#pragma unroll 1
  for (int cc = 0; cc < 64; cc += 16) {
    for (int fid = threadIdx.x; fid < 1536; fid += 128) {
      int r = fid / 512;
      int rem = fid - r * 512;
      int ww = rem >> 2;
      int cq = (rem & 3) * 4;
      int y = h + r - 1;
      float4 v = make_float4(0.f, 0.f, 0.f, 0.f);
      if ((unsigned)y < 128u)
        v = *(const float4*)&x[(((b * 128 + y) * 128 + ww) * 64) + cc + cq];
      xs[r][ww][cq + 0] = v.x;
      xs[r][ww][cq + 1] = v.y;
      xs[r][ww][cq + 2] = v.z;
      xs[r][ww][cq + 3] = v.w;
    }
    for (int idx = threadIdx.x; idx < 9 * 16 * 18; idx += 128) {
      int rs = idx / 288;
      ((float*)wofs)[idx] = Woff[idx + rs * 864 + cc * 18];
    }
    __syncthreads();

#pragma unroll 1
    for (int rs = 0; rs < 9; rs++) {
      int r = rs / 3;
      int s = rs - r * 3;
      int wp = w + s - 1;
      if ((unsigned)wp < 128u) {
#pragma unroll
        for (int c = 0; c < 16; c++) {
          float v = xs[r][wp][c];
#pragma unroll
          for (int o = 0; o < 18; o++) acc[o] += v * wofs[rs][c][o];
        }
      }
    }
    __syncthreads();
  }

  int base = (bh * 128 + w) * 18;
#pragma unroll
  for (int o = 0; o < 18; o++) g_off[base + o] = acc[o] + boff[o];
}

// ------------------------------------------------------------------
// K2: materialize sampled (pixel, ts, 64ch).
// One warp per (pixel, ts) iteration: weights computed once, channels
// loaded coalesced (float2 per lane -> 2 lines per corner).
// ------------------------------------------------------------------
__global__ __launch_bounds__(256) void sample_kernel(const float* __restrict__ x) {
  const int bh = blockIdx.x;
  const int b = bh >> 7, h = bh & 127;
  const int warp = threadIdx.x >> 5, lane = threadIdx.x & 31;
  const float* xb = x + ((size_t)b << 20);

  for (int t = warp; t < 128 * 9; t += 8) {
    int p = t / 9;
    int ts = t - p * 9;
    int pix = bh * 128 + p;
    float ox = g_off[pix * 18 + 2 * ts];
    float oy = g_off[pix * 18 + 2 * ts + 1];
    // reference: clip -> floor -> clipped-corner weights
    float lx = (float)(p + (ts % 3) - 1) + ox;
    float ly = (float)(h + (ts / 3) - 1) + oy;
    lx = fminf(fmaxf(lx, 0.f), 127.f);
    ly = fminf(fmaxf(ly, 0.f), 127.f);
    float x0f = floorf(lx), y0f = floorf(ly);
    int xi0 = (int)x0f, yi0 = (int)y0f;
    int xi1 = min(xi0 + 1, 127), yi1 = min(yi0 + 1, 127);
    float dx0 = lx - x0f, dy0 = ly - y0f;
    float dx1 = (float)xi1 - lx, dy1 = (float)yi1 - ly;
    float wa = dx1 * dy1, wb = dx1 * dy0, wc = dx0 * dy1, wd = dx0 * dy0;

    int r0 = yi0 << 13, r1 = yi1 << 13;
    int cx0 = xi0 << 6, cx1 = xi1 << 6;
    int cl = 2 * lane;
    float2 Ia = *(const float2*)&xb[r0 + cx0 + cl];
    float2 Ib = *(const float2*)&xb[r1 + cx0 + cl];
    float2 Ic = *(const float2*)&xb[r0 + cx1 + cl];
    float2 Id = *(const float2*)&xb[r1 + cx1 + cl];
    float2 rv;
    rv.x = wa * Ia.x + wb * Ib.x + wc * Ic.x + wd * Id.x;
    rv.y = wa * Ia.y + wb * Ib.y + wc * Ic.y + wd * Id.y;
    *(float2*)&g_samp[((size_t)pix * 9 + ts) * 64 + cl] = rv;
  }
}

#define FMA2(d, a, bb) \
  asm("fma.rn.f32x2 %0, %1, %2, %0;" : "+l"(d) : "l"(a), "l"(bb))

// ------------------------------------------------------------------
// K3: regular implicit GEMM over sampled.
// BM=128 (one row), BN=128, BK=8, 256 threads, 8x8 per thread.
// Packing: acc[m][n-pair]; A value duplicated via register MOV,
// B stored un-duplicated in smem (n-pairs load naturally).
// ------------------------------------------------------------------
__global__ __launch_bounds__(256, 2) void gemm_kernel(
    const float* __restrict__ Wm, const float* __restrict__ bias,
    float* __restrict__ out) {
  __shared__ __align__(16) float As[2][8][132];
  __shared__ __align__(16) float Bs[2][8][128];

  const int tid = threadIdx.x;
  const int bh = blockIdx.x;
  const int b = bh >> 7, h = bh & 127;
  const int tm8 = (tid >> 4) * 8;   // 8 output rows
  const int tn8 = (tid & 15) * 8;   // 8 output cols (4 n-pairs)
  const int apix = tid >> 1;        // A-load pixel
  const int akq = (tid & 1) * 4;    // A-load channel quad
  const int bk = tid >> 5;          // B-load k row
  const int bf = (tid & 31) * 4;    // B-load filter base

  unsigned long long acc[8][4];
#pragma unroll
  for (int j = 0; j < 4; j++) {
    float blo = bias[tn8 + 2 * j];
    float bhi = bias[tn8 + 2 * j + 1];
    unsigned long long d;
    asm("mov.b64 %0, {%1, %2};" : "=l"(d) : "f"(blo), "f"(bhi));
#pragma unroll
    for (int i = 0; i < 8; i++) acc[i][j] = d;
  }

  // A element from materialized sampled tensor (im2col over outer 3x3).
  auto loadA = [&](int cn) -> float4 {
    int tap = cn / 72;                 // outer tap
    int rem = cn - tap * 72;
    int ts = rem >> 3;                 // inner (bilinear) tap
    int cb = (cn & 7) * 8 + akq;       // channel base
    int r = tap / 3, s = tap - r * 3;
    int y = h + r - 1, wp = apix + s - 1;
    if ((unsigned)y < 128u && (unsigned)wp < 128u) {
      size_t idx = (((size_t)((b * 128 + y) * 128 + wp)) * 9 + ts) * 64 + cb;
      return *(const float4*)&g_samp[idx];
    }
    return make_float4(0.f, 0.f, 0.f, 0.f);
  };

  float4 av = loadA(0);
  float4 wv = *(const float4*)&Wm[(size_t)bk * 128 + bf];
  As[0][akq + 0][apix] = av.x;
  As[0][akq + 1][apix] = av.y;
  As[0][akq + 2][apix] = av.z;
  As[0][akq + 3][apix] = av.w;
  *(float4*)&Bs[0][bk][bf] = wv;
  __syncthreads();

  for (int cn = 0; cn < NCH; cn++) {
    const int cur = cn & 1;
    const bool more = (cn + 1 < NCH);
    if (more) {
      av = loadA(cn + 1);
      wv = *(const float4*)&Wm[(size_t)((cn + 1) * 8 + bk) * 128 + bf];
    }

#pragma unroll
    for (int k = 0; k < 8; k++) {
      const float* Ar = &As[cur][k][tm8];
      float4 a0 = *(const float4*)Ar;
      float4 a1 = *(const float4*)(Ar + 4);
      ulonglong2 bb0 = *(const ulonglong2*)&Bs[cur][k][tn8];
      ulonglong2 bb1 = *(const ulonglong2*)&Bs[cur][k][tn8 + 4];
      float am[8] = {a0.x, a0.y, a0.z, a0.w, a1.x, a1.y, a1.z, a1.w};
      unsigned long long bd[4] = {bb0.x, bb0.y, bb1.x, bb1.y};
#pragma unroll
      for (int i = 0; i < 8; i++) {
        unsigned long long ad;
        asm("mov.b64 %0, {%1, %1};" : "=l"(ad) : "f"(am[i]));
#pragma unroll
        for (int j = 0; j < 4; j++) FMA2(acc[i][j], ad, bd[j]);
      }
    }

    if (more) {
      const int nb = cur ^ 1;
      As[nb][akq + 0][apix] = av.x;
      As[nb][akq + 1][apix] = av.y;
      As[nb][akq + 2][apix] = av.z;
      As[nb][akq + 3][apix] = av.w;
      *(float4*)&Bs[nb][bk][bf] = wv;
    }
    __syncthreads();
  }

  // epilogue: acc[i][j] = {n=tn8+2j, n=tn8+2j+1} at row tm8+i
  float* outp = out + (size_t)bh * 16384;
#pragma unroll
  for (int i = 0; i < 8; i++) {
    float lo[4], hi[4];
#pragma unroll
    for (int j = 0; j < 4; j++)
      asm("mov.b64 {%0, %1}, %2;" : "=f"(lo[j]), "=f"(hi[j]) : "l"(acc[i][j]));
    int m = tm8 + i;
    *(float4*)&outp[m * 128 + tn8] = make_float4(lo[0], hi[0], lo[1], hi[1]);
    *(float4*)&outp[m * 128 + tn8 + 4] = make_float4(lo[2], hi[2], lo[3], hi[3]);
  }
}

extern "C" void kernel_launch(void* const* d_in, const int* in_sizes, int n_in,
                              void* d_out, int out_size) {
  (void)in_sizes;
  (void)n_in;
  (void)out_size;
  const float* x = (const float*)d_in[0];
  const float* Woff = (const float*)d_in[1];
  const float* boff = (const float*)d_in[2];
  const float* Wm = (const float*)d_in[3];
  const float* bias = (const float*)d_in[4];
  float* out = (float*)d_out;

  offsets_kernel<<<1024, 128>>>(x, Woff, boff);
  sample_kernel<<<1024, 256>>>(x);
  gemm_kernel<<<1024, 256>>>(Wm, bias, out);
}

// round 5
// speedup vs baseline: 16.4578x; 5.1904x over previous
#include <cuda_runtime.h>
#include <cuda_fp16.h>
#include <cstdint>

// x:(8,128,128,64) Woff:(3,3,64,18) boff:(18) W:(3,3,576,128)->(5184,128) b:(128)
// out:(8,128,128,128) f32

#define CHUNKS 81  // 5184/64; chunk q=(tap=q/9, ts=q%9), 64 channels

__device__ float g_off[8 * 128 * 128 * 18];
__device__ __half g_samp[8 * 128 * 128 * 9 * 64];   // 151MB, (pixel, ts, c)
__device__ __half g_wt[CHUNKS * 128 * 64];          // [q][n][c] K-major

__device__ __forceinline__ uint32_t smem_u32(const void* p) {
  uint32_t a;
  asm("{ .reg .u64 t; cvta.to.shared.u64 t, %1; cvt.u32.u64 %0, t; }"
      : "=r"(a) : "l"(p));
  return a;
}

// SW128 swizzle on byte offsets (128B rows): bits[6:4] ^= bits[9:7]
#define SWZ(o) ((o) ^ (((o) >> 3) & 0x70))

// ------------------------------------------------------------------
// K1: offsets conv3x3 + boff. One block per (b,h) row.
// ------------------------------------------------------------------
__global__ __launch_bounds__(128) void offsets_kernel(
    const float* __restrict__ x, const float* __restrict__ Woff,
    const float* __restrict__ boff) {
  __shared__ float xs[3][128][17];
  __shared__ float wofs[9][16][18];
  const int bh = blockIdx.x;
  const int b = bh >> 7, h = bh & 127;
  const int w = threadIdx.x;
  float acc[18];
#pragma unroll
  for (int o = 0; o < 18; o++) acc[o] = 0.f;
#pragma unroll 1
  for (int cc = 0; cc < 64; cc += 16) {
    for (int fid = threadIdx.x; fid < 1536; fid += 128) {
      int r = fid / 512;
      int rem = fid - r * 512;
      int ww = rem >> 2;
      int cq = (rem & 3) * 4;
      int y = h + r - 1;
      float4 v = make_float4(0.f, 0.f, 0.f, 0.f);
      if ((unsigned)y < 128u)
        v = *(const float4*)&x[(((b * 128 + y) * 128 + ww) * 64) + cc + cq];
      xs[r][ww][cq + 0] = v.x;
      xs[r][ww][cq + 1] = v.y;
      xs[r][ww][cq + 2] = v.z;
      xs[r][ww][cq + 3] = v.w;
    }
    for (int idx = threadIdx.x; idx < 9 * 16 * 18; idx += 128) {
      int rs = idx / 288;
      ((float*)wofs)[idx] = Woff[idx + rs * 864 + cc * 18];
    }
    __syncthreads();
#pragma unroll 1
    for (int rs = 0; rs < 9; rs++) {
      int r = rs / 3;
      int s = rs - r * 3;
      int wp = w + s - 1;
      if ((unsigned)wp < 128u) {
#pragma unroll
        for (int c = 0; c < 16; c++) {
          float v = xs[r][wp][c];
#pragma unroll
          for (int o = 0; o < 18; o++) acc[o] += v * wofs[rs][c][o];
        }
      }
    }
    __syncthreads();
  }
  int base = (bh * 128 + w) * 18;
#pragma unroll
  for (int o = 0; o < 18; o++) g_off[base + o] = acc[o] + boff[o];
}

// ------------------------------------------------------------------
// K2: bilinear sample -> fp16. One warp per (pixel, ts).
// ------------------------------------------------------------------
__global__ __launch_bounds__(256) void sample_kernel(const float* __restrict__ x) {
  const int bh = blockIdx.x;
  const int b = bh >> 7, h = bh & 127;
  const int warp = threadIdx.x >> 5, lane = threadIdx.x & 31;
  const float* xb = x + ((size_t)b << 20);

  for (int t = warp; t < 128 * 9; t += 8) {
    int p = t / 9;
    int ts = t - p * 9;
    int pix = bh * 128 + p;
    float ox = g_off[pix * 18 + 2 * ts];
    float oy = g_off[pix * 18 + 2 * ts + 1];
    float lx = (float)(p + (ts % 3) - 1) + ox;
    float ly = (float)(h + (ts / 3) - 1) + oy;
    lx = fminf(fmaxf(lx, 0.f), 127.f);
    ly = fminf(fmaxf(ly, 0.f), 127.f);
    float x0f = floorf(lx), y0f = floorf(ly);
    int xi0 = (int)x0f, yi0 = (int)y0f;
    int xi1 = min(xi0 + 1, 127), yi1 = min(yi0 + 1, 127);
    float dx0 = lx - x0f, dy0 = ly - y0f;
    float dx1 = (float)xi1 - lx, dy1 = (float)yi1 - ly;
    float wa = dx1 * dy1, wb = dx1 * dy0, wc = dx0 * dy1, wd = dx0 * dy0;

    int r0 = yi0 << 13, r1 = yi1 << 13;
    int cx0 = xi0 << 6, cx1 = xi1 << 6;
    int cl = 2 * lane;
    float2 Ia = *(const float2*)&xb[r0 + cx0 + cl];
    float2 Ib = *(const float2*)&xb[r1 + cx0 + cl];
    float2 Ic = *(const float2*)&xb[r0 + cx1 + cl];
    float2 Id = *(const float2*)&xb[r1 + cx1 + cl];
    float vx = wa * Ia.x + wb * Ib.x + wc * Ic.x + wd * Id.x;
    float vy = wa * Ia.y + wb * Ib.y + wc * Ic.y + wd * Id.y;
    *(__half2*)&g_samp[((size_t)pix * 9 + ts) * 64 + cl] =
        __floats2half2_rn(vx, vy);
  }
}

// ------------------------------------------------------------------
// K3: W (5184,128) -> fp16 [q][n][c]
// ------------------------------------------------------------------
__global__ __launch_bounds__(256) void wprep_kernel(const float* __restrict__ Wm) {
  int i = blockIdx.x * 256 + threadIdx.x;  // 81*128*64
  int c = i & 63;
  int n = (i >> 6) & 127;
  int q = i >> 13;
  g_wt[i] = __float2half(Wm[(q * 64 + c) * 128 + n]);
}

// ------------------------------------------------------------------
// K4: fp16 mma.sync implicit GEMM. One block per (b,h) row.
// M=128,N=128,K=5184. 8 warps, warp tile m64 x n32. cp.async 2-stage.
// Stage = A(128x64 fp16, 16KB) + B(128x64 fp16, 16KB) = 32KB.
// ------------------------------------------------------------------
__global__ __launch_bounds__(256, 2) void gemm_kernel(
    const float* __restrict__ bias, float* __restrict__ out) {
  extern __shared__ __align__(16) char smraw[];
  const uint32_t sb = smem_u32(smraw);
  const uint32_t tiles = (sb + 1023u) & ~1023u;

  const int tid = threadIdx.x, lane = tid & 31, wid = tid >> 5;
  const int bh = blockIdx.x;
  const int b = bh >> 7, h = bh & 127;

  // chunk loader (cp.async, zero-fill for halo rows)
  auto load_chunk = [&](int q, int st) {
    int tap = q / 9, ts = q - tap * 9;
    int r = tap / 3, s = tap - r * 3;
    int y = h + r - 1;
    uint32_t abase = tiles + (uint32_t)st * 32768u;
    uint32_t bbase = abase + 16384u;
#pragma unroll
    for (int j = 0; j < 4; j++) {
      int seg = j * 256 + tid;
      int arow = seg >> 3, acol = seg & 7;
      int wp = arow + s - 1;
      bool ok = ((unsigned)y < 128u) && ((unsigned)wp < 128u);
      const __half* src =
          ok ? g_samp + ((((size_t)((b * 128 + y) * 128 + wp)) * 9 + ts) * 64 +
                         acol * 8)
             : g_samp;
      uint32_t dst = abase + SWZ(arow * 128 + acol * 16);
      int sz = ok ? 16 : 0;
      asm volatile("cp.async.ca.shared.global [%0], [%1], 16, %2;" ::"r"(dst),
                   "l"(src), "r"(sz));
    }
#pragma unroll
    for (int j = 0; j < 4; j++) {
      int seg = j * 256 + tid;
      int brow = seg >> 3, bcol = seg & 7;
      const __half* src = g_wt + ((size_t)q * 8192 + brow * 64 + bcol * 8);
      uint32_t dst = bbase + SWZ(brow * 128 + bcol * 16);
      asm volatile("cp.async.ca.shared.global [%0], [%1], 16;" ::"r"(dst),
                   "l"(src));
    }
    asm volatile("cp.async.commit_group;" ::);
  };

  const int m0 = (wid & 1) * 64;
  const int n0 = (wid >> 1) * 32;

  float acc[4][4][4];
#pragma unroll
  for (int nt = 0; nt < 4; nt++) {
    int n = n0 + nt * 8 + 2 * (lane & 3);
    float b0 = bias[n], b1 = bias[n + 1];
#pragma unroll
    for (int mt = 0; mt < 4; mt++) {
      acc[mt][nt][0] = b0;
      acc[mt][nt][1] = b1;
      acc[mt][nt][2] = b0;
      acc[mt][nt][3] = b1;
    }
  }

  load_chunk(0, 0);

  for (int c = 0; c < CHUNKS; c++) {
    const int st = c & 1;
    if (c + 1 < CHUNKS) {
      load_chunk(c + 1, st ^ 1);
      asm volatile("cp.async.wait_group 1;" ::);
    } else {
      asm volatile("cp.async.wait_group 0;" ::);
    }
    __syncthreads();

    const uint32_t abase = tiles + (uint32_t)st * 32768u;
    const uint32_t bbase = abase + 16384u;
#pragma unroll
    for (int ks = 0; ks < 4; ks++) {
      uint32_t ar[4][4], br[4][2];
#pragma unroll
      for (int mt = 0; mt < 4; mt++) {
        int row = m0 + mt * 16 + (lane & 15);
        uint32_t addr = abase + SWZ(row * 128 + ks * 32 + ((lane >> 4) << 4));
        asm volatile(
            "ldmatrix.sync.aligned.m8n8.x4.shared.b16 {%0,%1,%2,%3}, [%4];"
            : "=r"(ar[mt][0]), "=r"(ar[mt][1]), "=r"(ar[mt][2]),
              "=r"(ar[mt][3])
            : "r"(addr));
      }
#pragma unroll
      for (int nt = 0; nt < 4; nt++) {
        int l = lane & 15;
        int row = n0 + nt * 8 + (l & 7);
        uint32_t addr = bbase + SWZ(row * 128 + ks * 32 + ((l >> 3) << 4));
        asm volatile("ldmatrix.sync.aligned.m8n8.x2.shared.b16 {%0,%1}, [%2];"
                     : "=r"(br[nt][0]), "=r"(br[nt][1])
                     : "r"(addr));
      }
#pragma unroll
      for (int mt = 0; mt < 4; mt++)
#pragma unroll
        for (int nt = 0; nt < 4; nt++) {
          asm volatile(
              "mma.sync.aligned.m16n8k16.row.col.f32.f16.f16.f32 "
              "{%0,%1,%2,%3}, {%4,%5,%6,%7}, {%8,%9}, {%0,%1,%2,%3};"
              : "+f"(acc[mt][nt][0]), "+f"(acc[mt][nt][1]),
                "+f"(acc[mt][nt][2]), "+f"(acc[mt][nt][3])
              : "r"(ar[mt][0]), "r"(ar[mt][1]), "r"(ar[mt][2]),
                "r"(ar[mt][3]), "r"(br[nt][0]), "r"(br[nt][1]));
        }
    }
    __syncthreads();
  }

  // epilogue
  float* ob = out + (size_t)bh * 16384;
#pragma unroll
  for (int mt = 0; mt < 4; mt++) {
    int row0 = m0 + mt * 16 + (lane >> 2);
#pragma unroll
    for (int nt = 0; nt < 4; nt++) {
      int n = n0 + nt * 8 + 2 * (lane & 3);
      *(float2*)&ob[row0 * 128 + n] =
          make_float2(acc[mt][nt][0], acc[mt][nt][1]);
      *(float2*)&ob[(row0 + 8) * 128 + n] =
          make_float2(acc[mt][nt][2], acc[mt][nt][3]);
    }
  }
}

extern "C" void kernel_launch(void* const* d_in, const int* in_sizes, int n_in,
                              void* d_out, int out_size) {
  (void)in_sizes;
  (void)n_in;
  (void)out_size;
  const float* x = (const float*)d_in[0];
  const float* Woff = (const float*)d_in[1];
  const float* boff = (const float*)d_in[2];
  const float* Wm = (const float*)d_in[3];
  const float* bias = (const float*)d_in[4];
  float* out = (float*)d_out;

  const int smem_bytes = 2 * 32768 + 1024;
  cudaFuncSetAttribute(gemm_kernel, cudaFuncAttributeMaxDynamicSharedMemorySize,
                       smem_bytes);

  offsets_kernel<<<1024, 128>>>(x, Woff, boff);
  sample_kernel<<<1024, 256>>>(x);
  wprep_kernel<<<2592, 256>>>(Wm);
  gemm_kernel<<<1024, 256, smem_bytes>>>(bias, out);
}

// round 6
// speedup vs baseline: 16.8977x; 1.0267x over previous
#include <cuda_runtime.h>
#include <cuda_fp16.h>
#include <cstdint>

// x:(8,128,128,64) Woff:(3,3,64,18) boff:(18) W:(3,3,576,128)->(5184,128) b:(128)
// out:(8,128,128,128) f32

#define CHUNKS 81  // 5184/64; chunk q=(tap=q/9, ts=q%9), 64 channels

__device__ float g_off[8 * 128 * 128 * 18];
__device__ __half g_xh[8 * 128 * 128 * 64];         // x in fp16 (16.8MB)
__device__ __half g_samp[8 * 128 * 128 * 9 * 64];   // (pixel, ts, c) 151MB
__device__ __half g_wt[CHUNKS * 128 * 64];          // [q][n][c] K-major

__device__ __forceinline__ uint32_t smem_u32(const void* p) {
  uint32_t a;
  asm("{ .reg .u64 t; cvta.to.shared.u64 t, %1; cvt.u32.u64 %0, t; }"
      : "=r"(a) : "l"(p));
  return a;
}

// SW128 swizzle on byte offsets (128B rows): bits[6:4] ^= bits[9:7]
#define SWZ(o) ((o) ^ (((o) >> 3) & 0x70))

// ------------------------------------------------------------------
// K0: x -> fp16
// ------------------------------------------------------------------
__global__ __launch_bounds__(256) void xh_kernel(const float* __restrict__ x) {
  int i = blockIdx.x * 256 + threadIdx.x;  // over 4.19M half2
  float2 v = *(const float2*)&x[2 * i];
  *(__half2*)&g_xh[2 * i] = __floats2half2_rn(v.x, v.y);
}

// ------------------------------------------------------------------
// K1: offsets conv3x3 + boff. One block per (b,h) row. (fp32 x)
// ------------------------------------------------------------------
__global__ __launch_bounds__(128) void offsets_kernel(
    const float* __restrict__ x, const float* __restrict__ Woff,
    const float* __restrict__ boff) {
  __shared__ float xs[3][128][17];
  __shared__ float wofs[9][16][18];
  const int bh = blockIdx.x;
  const int b = bh >> 7, h = bh & 127;
  const int w = threadIdx.x;
  float acc[18];
#pragma unroll
  for (int o = 0; o < 18; o++) acc[o] = 0.f;
#pragma unroll 1
  for (int cc = 0; cc < 64; cc += 16) {
    for (int fid = threadIdx.x; fid < 1536; fid += 128) {
      int r = fid / 512;
      int rem = fid - r * 512;
      int ww = rem >> 2;
      int cq = (rem & 3) * 4;
      int y = h + r - 1;
      float4 v = make_float4(0.f, 0.f, 0.f, 0.f);
      if ((unsigned)y < 128u)
        v = *(const float4*)&x[(((b * 128 + y) * 128 + ww) * 64) + cc + cq];
      xs[r][ww][cq + 0] = v.x;
      xs[r][ww][cq + 1] = v.y;
      xs[r][ww][cq + 2] = v.z;
      xs[r][ww][cq + 3] = v.w;
    }
    for (int idx = threadIdx.x; idx < 9 * 16 * 18; idx += 128) {
      int rs = idx / 288;
      ((float*)wofs)[idx] = Woff[idx + rs * 864 + cc * 18];
    }
    __syncthreads();
#pragma unroll 1
    for (int rs = 0; rs < 9; rs++) {
      int r = rs / 3;
      int s = rs - r * 3;
      int wp = w + s - 1;
      if ((unsigned)wp < 128u) {
#pragma unroll
        for (int c = 0; c < 16; c++) {
          float v = xs[r][wp][c];
#pragma unroll
          for (int o = 0; o < 18; o++) acc[o] += v * wofs[rs][c][o];
        }
      }
    }
    __syncthreads();
  }
  int base = (bh * 128 + w) * 18;
#pragma unroll
  for (int o = 0; o < 18; o++) g_off[base + o] = acc[o] + boff[o];
}

// ------------------------------------------------------------------
// K2: bilinear sample (fp16 x) -> fp16. One warp per (pixel, ts).
// ------------------------------------------------------------------
__global__ __launch_bounds__(256) void sample_kernel() {
  const int bh = blockIdx.x;
  const int b = bh >> 7, h = bh & 127;
  const int warp = threadIdx.x >> 5, lane = threadIdx.x & 31;
  const __half* xb = g_xh + ((size_t)b << 20);

  for (int t = warp; t < 128 * 9; t += 8) {
    int p = t / 9;
    int ts = t - p * 9;
    int pix = bh * 128 + p;
    float ox = g_off[pix * 18 + 2 * ts];
    float oy = g_off[pix * 18 + 2 * ts + 1];
    float lx = (float)(p + (ts % 3) - 1) + ox;
    float ly = (float)(h + (ts / 3) - 1) + oy;
    lx = fminf(fmaxf(lx, 0.f), 127.f);
    ly = fminf(fmaxf(ly, 0.f), 127.f);
    float x0f = floorf(lx), y0f = floorf(ly);
    int xi0 = (int)x0f, yi0 = (int)y0f;
    int xi1 = min(xi0 + 1, 127), yi1 = min(yi0 + 1, 127);
    float dx0 = lx - x0f, dy0 = ly - y0f;
    float dx1 = (float)xi1 - lx, dy1 = (float)yi1 - ly;
    float wa = dx1 * dy1, wb = dx1 * dy0, wc = dx0 * dy1, wd = dx0 * dy0;

    int r0 = yi0 << 13, r1 = yi1 << 13;
    int cx0 = xi0 << 6, cx1 = xi1 << 6;
    int cl = 2 * lane;
    float2 Ia = __half22float2(*(const __half2*)&xb[r0 + cx0 + cl]);
    float2 Ib = __half22float2(*(const __half2*)&xb[r1 + cx0 + cl]);
    float2 Ic = __half22float2(*(const __half2*)&xb[r0 + cx1 + cl]);
    float2 Id = __half22float2(*(const __half2*)&xb[r1 + cx1 + cl]);
    float vx = wa * Ia.x + wb * Ib.x + wc * Ic.x + wd * Id.x;
    float vy = wa * Ia.y + wb * Ib.y + wc * Ic.y + wd * Id.y;
    *(__half2*)&g_samp[((size_t)pix * 9 + ts) * 64 + cl] =
        __floats2half2_rn(vx, vy);
  }
}

// ------------------------------------------------------------------
// K3: W (5184,128) -> fp16 [q][n][c]
// ------------------------------------------------------------------
__global__ __launch_bounds__(256) void wprep_kernel(const float* __restrict__ Wm) {
  int i = blockIdx.x * 256 + threadIdx.x;  // 81*128*64
  int c = i & 63;
  int n = (i >> 6) & 127;
  int q = i >> 13;
  g_wt[i] = __float2half(Wm[(q * 64 + c) * 128 + n]);
}

// ------------------------------------------------------------------
// K4: fp16 mma.sync implicit GEMM. One block per (b,h) row.
// M=128,N=128,K=5184. 8 warps m64xn32. 3-stage cp.async, 1 sync/chunk.
// Stage = A(16KB) + B(16KB) = 32KB; 3 stages = 96KB; 2 CTA/SM.
// ------------------------------------------------------------------
__global__ __launch_bounds__(256, 2) void gemm_kernel(
    const float* __restrict__ bias, float* __restrict__ out) {
  extern __shared__ __align__(16) char smraw[];
  const uint32_t sb = smem_u32(smraw);
  const uint32_t tiles = (sb + 1023u) & ~1023u;

  const int tid = threadIdx.x, lane = tid & 31, wid = tid >> 5;
  const int bh = blockIdx.x;
  const int b = bh >> 7, h = bh & 127;

  auto load_chunk = [&](int q, int st) {
    int tap = q / 9, ts = q - tap * 9;
    int r = tap / 3, s = tap - r * 3;
    int y = h + r - 1;
    uint32_t abase = tiles + (uint32_t)st * 32768u;
    uint32_t bbase = abase + 16384u;
#pragma unroll
    for (int j = 0; j < 4; j++) {
      int seg = j * 256 + tid;
      int arow = seg >> 3, acol = seg & 7;
      int wp = arow + s - 1;
      bool ok = ((unsigned)y < 128u) && ((unsigned)wp < 128u);
      const __half* src =
          ok ? g_samp + ((((size_t)((b * 128 + y) * 128 + wp)) * 9 + ts) * 64 +
                         acol * 8)
             : g_samp;
      uint32_t dst = abase + SWZ(arow * 128 + acol * 16);
      int sz = ok ? 16 : 0;
      asm volatile("cp.async.ca.shared.global [%0], [%1], 16, %2;" ::"r"(dst),
                   "l"(src), "r"(sz));
    }
#pragma unroll
    for (int j = 0; j < 4; j++) {
      int seg = j * 256 + tid;
      int brow = seg >> 3, bcol = seg & 7;
      const __half* src = g_wt + ((size_t)q * 8192 + brow * 64 + bcol * 8);
      uint32_t dst = bbase + SWZ(brow * 128 + bcol * 16);
      asm volatile("cp.async.ca.shared.global [%0], [%1], 16;" ::"r"(dst),
                   "l"(src));
    }
    asm volatile("cp.async.commit_group;" ::);
  };

  const int m0 = (wid & 1) * 64;
  const int n0 = (wid >> 1) * 32;

  float acc[4][4][4];
#pragma unroll
  for (int nt = 0; nt < 4; nt++) {
    int n = n0 + nt * 8 + 2 * (lane & 3);
    float b0 = bias[n], b1 = bias[n + 1];
#pragma unroll
    for (int mt = 0; mt < 4; mt++) {
      acc[mt][nt][0] = b0;
      acc[mt][nt][1] = b1;
      acc[mt][nt][2] = b0;
      acc[mt][nt][3] = b1;
    }
  }

  load_chunk(0, 0);
  load_chunk(1, 1);

  for (int c = 0; c < CHUNKS; c++) {
    const int st = c % 3;
    if (c + 1 < CHUNKS)
      asm volatile("cp.async.wait_group 1;" ::);  // group c complete
    else
      asm volatile("cp.async.wait_group 0;" ::);
    __syncthreads();  // all threads done reading stage (c+2)%3's old chunk
    if (c + 2 < CHUNKS) load_chunk(c + 2, (c + 2) % 3);

    const uint32_t abase = tiles + (uint32_t)st * 32768u;
    const uint32_t bbase = abase + 16384u;
#pragma unroll
    for (int ks = 0; ks < 4; ks++) {
      uint32_t ar[4][4], br[4][2];
#pragma unroll
      for (int mt = 0; mt < 4; mt++) {
        int row = m0 + mt * 16 + (lane & 15);
        uint32_t addr = abase + SWZ(row * 128 + ks * 32 + ((lane >> 4) << 4));
        asm volatile(
            "ldmatrix.sync.aligned.m8n8.x4.shared.b16 {%0,%1,%2,%3}, [%4];"
            : "=r"(ar[mt][0]), "=r"(ar[mt][1]), "=r"(ar[mt][2]),
              "=r"(ar[mt][3])
            : "r"(addr));
      }
      // B: two n-tiles per ldmatrix.x4
#pragma unroll
      for (int np = 0; np < 2; np++) {
        int rowb = n0 + np * 16 + ((lane >> 4) << 3) + (lane & 7);
        uint32_t addr =
            bbase + SWZ(rowb * 128 + ks * 32 + (((lane >> 3) & 1) << 4));
        asm volatile(
            "ldmatrix.sync.aligned.m8n8.x4.shared.b16 {%0,%1,%2,%3}, [%4];"
            : "=r"(br[2 * np][0]), "=r"(br[2 * np][1]),
              "=r"(br[2 * np + 1][0]), "=r"(br[2 * np + 1][1])
            : "r"(addr));
      }
#pragma unroll
      for (int mt = 0; mt < 4; mt++)
#pragma unroll
        for (int nt = 0; nt < 4; nt++) {
          asm volatile(
              "mma.sync.aligned.m16n8k16.row.col.f32.f16.f16.f32 "
              "{%0,%1,%2,%3}, {%4,%5,%6,%7}, {%8,%9}, {%0,%1,%2,%3};"
              : "+f"(acc[mt][nt][0]), "+f"(acc[mt][nt][1]),
                "+f"(acc[mt][nt][2]), "+f"(acc[mt][nt][3])
              : "r"(ar[mt][0]), "r"(ar[mt][1]), "r"(ar[mt][2]),
                "r"(ar[mt][3]), "r"(br[nt][0]), "r"(br[nt][1]));
        }
    }
  }

  // epilogue
  float* ob = out + (size_t)bh * 16384;
#pragma unroll
  for (int mt = 0; mt < 4; mt++) {
    int row0 = m0 + mt * 16 + (lane >> 2);
#pragma unroll
    for (int nt = 0; nt < 4; nt++) {
      int n = n0 + nt * 8 + 2 * (lane & 3);
      *(float2*)&ob[row0 * 128 + n] =
          make_float2(acc[mt][nt][0], acc[mt][nt][1]);
      *(float2*)&ob[(row0 + 8) * 128 + n] =
          make_float2(acc[mt][nt][2], acc[mt][nt][3]);
    }
  }
}

extern "C" void kernel_launch(void* const* d_in, const int* in_sizes, int n_in,
                              void* d_out, int out_size) {
  (void)in_sizes;
  (void)n_in;
  (void)out_size;
  const float* x = (const float*)d_in[0];
  const float* Woff = (const float*)d_in[1];
  const float* boff = (const float*)d_in[2];
  const float* Wm = (const float*)d_in[3];
  const float* bias = (const float*)d_in[4];
  float* out = (float*)d_out;

  const int smem_bytes = 3 * 32768 + 1024;
  cudaFuncSetAttribute(gemm_kernel, cudaFuncAttributeMaxDynamicSharedMemorySize,
                       smem_bytes);

  xh_kernel<<<16384, 256>>>(x);
  offsets_kernel<<<1024, 128>>>(x, Woff, boff);
  sample_kernel<<<1024, 256>>>();
  wprep_kernel<<<2592, 256>>>(Wm);
  gemm_kernel<<<1024, 256, smem_bytes>>>(bias, out);
}